// round 7
// baseline (speedup 1.0000x reference)
#include <cuda_runtime.h>
#include <cuda_bf16.h>

#define BB 1024
#define TT 256
#define VV 256
#define HH 32

// hs scratch, plain layout: g_hs[row][k], row = t*B + b  (33.5 MB)
__device__ float g_hs[TT * BB * HH];

__device__ __forceinline__ float htanh(float x) {
    float y;
    asm("tanh.approx.f32 %0, %1;" : "=f"(y) : "f"(x));
    return y;
}

// ---------------------------------------------------------------------------
// Kernel A: embedding gather + recurrence. One warp per batch element,
// h[j] in lane j; h broadcast via double-buffered SMEM vector. Plain stores.
// ---------------------------------------------------------------------------
__global__ void __launch_bounds__(256)
rnn_recurrence(const int* __restrict__ X, const float* __restrict__ Wxh,
               const float* __restrict__ Whh, const float* __restrict__ bh)
{
    __shared__ float sWxh[VV * HH];       // 32 KB
    __shared__ int   sX[8][TT];           // 8 KB
    __shared__ float sH[2][8][HH];        // 2 KB double-buffered h vectors

    const int tid  = threadIdx.x;
    const int lane = tid & 31;
    const int warp = tid >> 5;
    const int b    = blockIdx.x * 8 + warp;

    {
        const float4* s = (const float4*)Wxh;
        float4*       d = (float4*)sWxh;
        #pragma unroll
        for (int i = tid; i < (VV * HH) / 4; i += 256) d[i] = s[i];
    }
    {
        const int4* s = (const int4*)(X + (long)blockIdx.x * 8 * TT);
        int4*       d = (int4*)&sX[0][0];
        #pragma unroll
        for (int i = tid; i < (8 * TT) / 4; i += 256) d[i] = s[i];
    }

    float w[HH];
    #pragma unroll
    for (int i = 0; i < HH; i++) w[i] = Whh[i * HH + lane];
    const float bhv = bh[lane];

    sH[0][warp][lane] = 0.f;
    __syncthreads();

    float* outp = g_hs + (long)b * HH + lane;

    int   tok = sX[warp][0];
    float xe  = sWxh[tok * HH + lane];

    #pragma unroll 2
    for (int t = 0; t < TT; t++) {
        const int tokn = sX[warp][(t + 1) & (TT - 1)];

        const float4* hr = (const float4*)&sH[t & 1][warp][0];
        float4 hv[8];
        #pragma unroll
        for (int k = 0; k < 8; k++) hv[k] = hr[k];

        float a[8];
        #pragma unroll
        for (int k = 0; k < 8; k++) a[k] = 0.f;
        #pragma unroll
        for (int k = 0; k < 8; k += 2) {
            a[k+0] = fmaf(hv[k+0].x, w[4*k + 0], a[k+0]);
            a[k+1] = fmaf(hv[k+0].y, w[4*k + 1], a[k+1]);
            a[k+0] = fmaf(hv[k+0].z, w[4*k + 2], a[k+0]);
            a[k+1] = fmaf(hv[k+0].w, w[4*k + 3], a[k+1]);
            a[k+0] = fmaf(hv[k+1].x, w[4*k + 4], a[k+0]);
            a[k+1] = fmaf(hv[k+1].y, w[4*k + 5], a[k+1]);
            a[k+0] = fmaf(hv[k+1].z, w[4*k + 6], a[k+0]);
            a[k+1] = fmaf(hv[k+1].w, w[4*k + 7], a[k+1]);
        }
        float s = (xe + bhv)
                + (((a[0] + a[1]) + (a[2] + a[3]))
                +  ((a[4] + a[5]) + (a[6] + a[7])));

        xe = sWxh[tokn * HH + lane];

        const float h = htanh(s);
        sH[(t + 1) & 1][warp][lane] = h;
        outp[(long)t * (BB * HH)] = h;          // coalesced 128B per warp
        __syncwarp();
    }
}

// ---------------------------------------------------------------------------
// tf32 helpers
// ---------------------------------------------------------------------------
__device__ __forceinline__ unsigned tf32_of(float x) {
    unsigned r;
    asm("cvt.rna.tf32.f32 %0, %1;" : "=r"(r) : "f"(x));
    return r;
}

__device__ __forceinline__ void mma_tf32(
    float& c0, float& c1, float& c2, float& c3,
    unsigned a0, unsigned a1, unsigned a2, unsigned a3,
    unsigned b0, unsigned b1)
{
    asm("mma.sync.aligned.m16n8k8.row.col.f32.tf32.tf32.f32 "
        "{%0,%1,%2,%3}, {%4,%5,%6,%7}, {%8,%9}, {%0,%1,%2,%3};"
        : "+f"(c0), "+f"(c1), "+f"(c2), "+f"(c3)
        : "r"(a0), "r"(a1), "r"(a2), "r"(a3), "r"(b0), "r"(b1));
}

// ---------------------------------------------------------------------------
// Kernel B: logits = hs[262144,32] @ W_hq[32,256] + bq, via m16n8k8 tf32 mma
// with 3-pass hi/lo split (full fp32 accuracy).
// 512 blocks x 8 chunks x 64 rows. Warp (mstrip, nhalf): m16 x n128.
// W_hq pre-permuted once per block into fragment-order SMEM:
//   sWfrag[nt][kc][lane] = (whi_b0, whi_b1, wlo_b0, wlo_b1)  (LDS.128, no conflicts)
// A fragments LDG'd from plain g_hs (rows read once). C init = bias.
// ---------------------------------------------------------------------------
#define NCHUNKS 8
#define CROWS   64

__global__ void __launch_bounds__(256)
rnn_logits(const float* __restrict__ Whq, const float* __restrict__ bq,
           float* __restrict__ out)
{
    __shared__ float4 sWfrag[32 * 4 * 32];   // 64 KB: [ntile][kc][lane]
    __shared__ float  sbq[VV];               // 1 KB

    const int tid  = threadIdx.x;
    const int lane = tid & 31;
    const int warp = tid >> 5;
    const int gid  = lane >> 2;   // groupID (row within fragment)
    const int tig  = lane & 3;    // thread-in-group (col within fragment)

    // Build fragment-ordered, hi/lo-split W. 4096 entries, 16 per thread.
    for (int i = tid; i < 32 * 4 * 32; i += 256) {
        const int l_  = i & 31;
        const int kc_ = (i >> 5) & 3;
        const int nt_ = i >> 7;
        const int tg  = l_ & 3;
        const int n   = nt_ * 8 + (l_ >> 2);
        const float w0 = Whq[(kc_ * 8 + tg) * VV + n];
        const float w1 = Whq[(kc_ * 8 + tg + 4) * VV + n];
        const unsigned h0 = tf32_of(w0);
        const unsigned h1 = tf32_of(w1);
        const unsigned l0 = tf32_of(w0 - __uint_as_float(h0));
        const unsigned l1 = tf32_of(w1 - __uint_as_float(h1));
        sWfrag[i] = make_float4(__uint_as_float(h0), __uint_as_float(h1),
                                __uint_as_float(l0), __uint_as_float(l1));
    }
    if (tid < VV / 4) ((float4*)sbq)[tid] = ((const float4*)bq)[tid];
    __syncthreads();

    const int mstrip = warp >> 1;     // 0..3
    const int nhalf  = warp & 1;      // 0..1

    for (int c = 0; c < NCHUNKS; c++) {
        const long rowbase = (long)blockIdx.x * (NCHUNKS * CROWS)
                           + c * CROWS + mstrip * 16;
        const long r0 = rowbase + gid;
        const long r1 = r0 + 8;

        // A fragments (hi/lo) for 4 k-chunks
        unsigned ahi[4][4], alo[4][4];
        #pragma unroll
        for (int kc = 0; kc < 4; kc++) {
            const float f0 = g_hs[r0 * HH + kc * 8 + tig];
            const float f1 = g_hs[r1 * HH + kc * 8 + tig];
            const float f2 = g_hs[r0 * HH + kc * 8 + tig + 4];
            const float f3 = g_hs[r1 * HH + kc * 8 + tig + 4];
            ahi[kc][0] = tf32_of(f0);
            ahi[kc][1] = tf32_of(f1);
            ahi[kc][2] = tf32_of(f2);
            ahi[kc][3] = tf32_of(f3);
            alo[kc][0] = tf32_of(f0 - __uint_as_float(ahi[kc][0]));
            alo[kc][1] = tf32_of(f1 - __uint_as_float(ahi[kc][1]));
            alo[kc][2] = tf32_of(f2 - __uint_as_float(ahi[kc][2]));
            alo[kc][3] = tf32_of(f3 - __uint_as_float(ahi[kc][3]));
        }

        // output row pointers (row = t*B + b -> out[b][t][:])
        const int t0 = (int)(r0 >> 10), b0i = (int)(r0 & 1023);
        const int t1 = (int)(r1 >> 10), b1i = (int)(r1 & 1023);
        float* o0 = out + ((long)b0i * TT + t0) * VV;
        float* o1 = out + ((long)b1i * TT + t1) * VV;

        #pragma unroll
        for (int nt = 0; nt < 16; nt++) {
            const int n0 = nhalf * 128 + nt * 8;

            // C init from bias (c2/c3 share cols with c0/c1)
            const float2 bqp = *(const float2*)&sbq[n0 + 2 * tig];
            float c0 = bqp.x, c1 = bqp.y, c2 = bqp.x, c3 = bqp.y;

            const float4* wf = &sWfrag[((nhalf * 16 + nt) * 4) * 32 + lane];
            #pragma unroll
            for (int kc = 0; kc < 4; kc++) {
                const float4 w = wf[kc * 32];         // LDS.128, conflict-free
                const unsigned wh0 = __float_as_uint(w.x);
                const unsigned wh1 = __float_as_uint(w.y);
                const unsigned wl0 = __float_as_uint(w.z);
                const unsigned wl1 = __float_as_uint(w.w);
                mma_tf32(c0, c1, c2, c3,
                         ahi[kc][0], ahi[kc][1], ahi[kc][2], ahi[kc][3],
                         wh0, wh1);
                mma_tf32(c0, c1, c2, c3,
                         ahi[kc][0], ahi[kc][1], ahi[kc][2], ahi[kc][3],
                         wl0, wl1);
                mma_tf32(c0, c1, c2, c3,
                         alo[kc][0], alo[kc][1], alo[kc][2], alo[kc][3],
                         wh0, wh1);
            }

            *(float2*)(o0 + n0 + 2 * tig) = make_float2(c0, c1);
            *(float2*)(o1 + n0 + 2 * tig) = make_float2(c2, c3);
        }
    }
}

// ---------------------------------------------------------------------------
// kernel_launch
// inputs: 0:X int32[B,T]  1:W_xh f32[V,H]  2:W_hh f32[H,H]  3:b_h f32[H]
//         4:W_hq f32[H,V] 5:b_q f32[V]     out: f32[B,T,V]
// ---------------------------------------------------------------------------
extern "C" void kernel_launch(void* const* d_in, const int* in_sizes, int n_in,
                              void* d_out, int out_size)
{
    const int*   X   = (const int*)d_in[0];
    const float* Wxh = (const float*)d_in[1];
    const float* Whh = (const float*)d_in[2];
    const float* bh  = (const float*)d_in[3];
    const float* Whq = (const float*)d_in[4];
    const float* bq  = (const float*)d_in[5];
    float*       out = (float*)d_out;

    rnn_recurrence<<<BB / 8, 256>>>(X, Wxh, Whh, bh);
    rnn_logits<<<(TT * BB) / (NCHUNKS * CROWS), 256>>>(Whq, bq, out);
}

// round 8
// speedup vs baseline: 1.3247x; 1.3247x over previous
#include <cuda_runtime.h>
#include <cuda_bf16.h>

#define BB 1024
#define TT 256
#define VV 256
#define HH 32

// hs scratch, plain layout: g_hs[row][k], row = t*B + b  (33.5 MB)
__device__ float g_hs[TT * BB * HH];

__device__ __forceinline__ float htanh(float x) {
    float y;
    asm("tanh.approx.f32 %0, %1;" : "=f"(y) : "f"(x));
    return y;
}

// ---------------------------------------------------------------------------
// Kernel A: embedding gather + recurrence (unchanged, ~27us).
// ---------------------------------------------------------------------------
__global__ void __launch_bounds__(256)
rnn_recurrence(const int* __restrict__ X, const float* __restrict__ Wxh,
               const float* __restrict__ Whh, const float* __restrict__ bh)
{
    __shared__ float sWxh[VV * HH];       // 32 KB
    __shared__ int   sX[8][TT];           // 8 KB
    __shared__ float sH[2][8][HH];        // 2 KB double-buffered h vectors

    const int tid  = threadIdx.x;
    const int lane = tid & 31;
    const int warp = tid >> 5;
    const int b    = blockIdx.x * 8 + warp;

    {
        const float4* s = (const float4*)Wxh;
        float4*       d = (float4*)sWxh;
        #pragma unroll
        for (int i = tid; i < (VV * HH) / 4; i += 256) d[i] = s[i];
    }
    {
        const int4* s = (const int4*)(X + (long)blockIdx.x * 8 * TT);
        int4*       d = (int4*)&sX[0][0];
        #pragma unroll
        for (int i = tid; i < (8 * TT) / 4; i += 256) d[i] = s[i];
    }

    float w[HH];
    #pragma unroll
    for (int i = 0; i < HH; i++) w[i] = Whh[i * HH + lane];
    const float bhv = bh[lane];

    sH[0][warp][lane] = 0.f;
    __syncthreads();

    float* outp = g_hs + (long)b * HH + lane;

    int   tok = sX[warp][0];
    float xe  = sWxh[tok * HH + lane];

    #pragma unroll 2
    for (int t = 0; t < TT; t++) {
        const int tokn = sX[warp][(t + 1) & (TT - 1)];

        const float4* hr = (const float4*)&sH[t & 1][warp][0];
        float4 hv[8];
        #pragma unroll
        for (int k = 0; k < 8; k++) hv[k] = hr[k];

        float a[8];
        #pragma unroll
        for (int k = 0; k < 8; k++) a[k] = 0.f;
        #pragma unroll
        for (int k = 0; k < 8; k += 2) {
            a[k+0] = fmaf(hv[k+0].x, w[4*k + 0], a[k+0]);
            a[k+1] = fmaf(hv[k+0].y, w[4*k + 1], a[k+1]);
            a[k+0] = fmaf(hv[k+0].z, w[4*k + 2], a[k+0]);
            a[k+1] = fmaf(hv[k+0].w, w[4*k + 3], a[k+1]);
            a[k+0] = fmaf(hv[k+1].x, w[4*k + 4], a[k+0]);
            a[k+1] = fmaf(hv[k+1].y, w[4*k + 5], a[k+1]);
            a[k+0] = fmaf(hv[k+1].z, w[4*k + 6], a[k+0]);
            a[k+1] = fmaf(hv[k+1].w, w[4*k + 7], a[k+1]);
        }
        float s = (xe + bhv)
                + (((a[0] + a[1]) + (a[2] + a[3]))
                +  ((a[4] + a[5]) + (a[6] + a[7])));

        xe = sWxh[tokn * HH + lane];

        const float h = htanh(s);
        sH[(t + 1) & 1][warp][lane] = h;
        outp[(long)t * (BB * HH)] = h;
        __syncwarp();
    }
}

// ---------------------------------------------------------------------------
// tf32 helpers
// ---------------------------------------------------------------------------
__device__ __forceinline__ unsigned tf32_of(float x) {
    unsigned r;
    asm("cvt.rna.tf32.f32 %0, %1;" : "=r"(r) : "f"(x));
    return r;
}

__device__ __forceinline__ void mma_tf32(
    float* c,
    const unsigned* a,
    unsigned b0, unsigned b1)
{
    asm("mma.sync.aligned.m16n8k8.row.col.f32.tf32.tf32.f32 "
        "{%0,%1,%2,%3}, {%4,%5,%6,%7}, {%8,%9}, {%0,%1,%2,%3};"
        : "+f"(c[0]), "+f"(c[1]), "+f"(c[2]), "+f"(c[3])
        : "r"(a[0]), "r"(a[1]), "r"(a[2]), "r"(a[3]), "r"(b0), "r"(b1));
}

// ---------------------------------------------------------------------------
// Kernel B: logits = hs[262144,32] @ W_hq[32,256] + bq, m16n8k8 tf32 mma,
// 3-pass hi/lo split. Round-7 arithmetic; round-8 scheduling:
//   - ntiles processed in groups of 4 with 4 independent accumulator sets
//     (mma dependency distance 4)
//   - __launch_bounds__(256,2): regs capped at 128 -> 2 blocks/SM
// ---------------------------------------------------------------------------
#define NCHUNKS 8
#define CROWS   64

__global__ void __launch_bounds__(256, 2)
rnn_logits(const float* __restrict__ Whq, const float* __restrict__ bq,
           float* __restrict__ out)
{
    __shared__ float4 sWfrag[32 * 4 * 32];   // 64 KB: [ntile][kc][lane]
    __shared__ float  sbq[VV];               // 1 KB

    const int tid  = threadIdx.x;
    const int lane = tid & 31;
    const int warp = tid >> 5;
    const int gid  = lane >> 2;   // row within fragment
    const int tig  = lane & 3;    // col within fragment

    // Build fragment-ordered, hi/lo-split W (once per block).
    for (int i = tid; i < 32 * 4 * 32; i += 256) {
        const int l_  = i & 31;
        const int kc_ = (i >> 5) & 3;
        const int nt_ = i >> 7;
        const int tg  = l_ & 3;
        const int n   = nt_ * 8 + (l_ >> 2);
        const float w0 = Whq[(kc_ * 8 + tg) * VV + n];
        const float w1 = Whq[(kc_ * 8 + tg + 4) * VV + n];
        const unsigned h0 = tf32_of(w0);
        const unsigned h1 = tf32_of(w1);
        const unsigned l0 = tf32_of(w0 - __uint_as_float(h0));
        const unsigned l1 = tf32_of(w1 - __uint_as_float(h1));
        sWfrag[i] = make_float4(__uint_as_float(h0), __uint_as_float(h1),
                                __uint_as_float(l0), __uint_as_float(l1));
    }
    if (tid < VV / 4) ((float4*)sbq)[tid] = ((const float4*)bq)[tid];
    __syncthreads();

    const int mstrip = warp >> 1;     // 0..3
    const int nhalf  = warp & 1;      // 0..1

    for (int c = 0; c < NCHUNKS; c++) {
        const long rowbase = (long)blockIdx.x * (NCHUNKS * CROWS)
                           + c * CROWS + mstrip * 16;
        const long r0 = rowbase + gid;
        const long r1 = r0 + 8;

        // A fragments (hi/lo) for 4 k-chunks: 32 regs
        unsigned ahi[4][4], alo[4][4];
        #pragma unroll
        for (int kc = 0; kc < 4; kc++) {
            const float f0 = g_hs[r0 * HH + kc * 8 + tig];
            const float f1 = g_hs[r1 * HH + kc * 8 + tig];
            const float f2 = g_hs[r0 * HH + kc * 8 + tig + 4];
            const float f3 = g_hs[r1 * HH + kc * 8 + tig + 4];
            ahi[kc][0] = tf32_of(f0);
            ahi[kc][1] = tf32_of(f1);
            ahi[kc][2] = tf32_of(f2);
            ahi[kc][3] = tf32_of(f3);
            alo[kc][0] = tf32_of(f0 - __uint_as_float(ahi[kc][0]));
            alo[kc][1] = tf32_of(f1 - __uint_as_float(ahi[kc][1]));
            alo[kc][2] = tf32_of(f2 - __uint_as_float(ahi[kc][2]));
            alo[kc][3] = tf32_of(f3 - __uint_as_float(ahi[kc][3]));
        }

        const int t0 = (int)(r0 >> 10), b0i = (int)(r0 & 1023);
        const int t1 = (int)(r1 >> 10), b1i = (int)(r1 & 1023);
        float* o0 = out + ((long)b0i * TT + t0) * VV;
        float* o1 = out + ((long)b1i * TT + t1) * VV;

        // 4 groups of 4 ntiles; 4 independent accumulator sets per group
        #pragma unroll 1
        for (int g = 0; g < 4; g++) {
            float cc[4][4];
            #pragma unroll
            for (int q = 0; q < 4; q++) {
                const int n0 = nhalf * 128 + (g * 4 + q) * 8;
                const float2 bqp = *(const float2*)&sbq[n0 + 2 * tig];
                cc[q][0] = bqp.x; cc[q][1] = bqp.y;
                cc[q][2] = bqp.x; cc[q][3] = bqp.y;
            }

            #pragma unroll
            for (int kc = 0; kc < 4; kc++) {
                float4 w[4];
                #pragma unroll
                for (int q = 0; q < 4; q++)
                    w[q] = sWfrag[((nhalf * 16 + g * 4 + q) * 4 + kc) * 32 + lane];

                // pass 1: ahi * whi   (independent across q)
                #pragma unroll
                for (int q = 0; q < 4; q++)
                    mma_tf32(cc[q], ahi[kc],
                             __float_as_uint(w[q].x), __float_as_uint(w[q].y));
                // pass 2: ahi * wlo
                #pragma unroll
                for (int q = 0; q < 4; q++)
                    mma_tf32(cc[q], ahi[kc],
                             __float_as_uint(w[q].z), __float_as_uint(w[q].w));
                // pass 3: alo * whi
                #pragma unroll
                for (int q = 0; q < 4; q++)
                    mma_tf32(cc[q], alo[kc],
                             __float_as_uint(w[q].x), __float_as_uint(w[q].y));
            }

            #pragma unroll
            for (int q = 0; q < 4; q++) {
                const int n0 = nhalf * 128 + (g * 4 + q) * 8;
                *(float2*)(o0 + n0 + 2 * tig) = make_float2(cc[q][0], cc[q][1]);
                *(float2*)(o1 + n0 + 2 * tig) = make_float2(cc[q][2], cc[q][3]);
            }
        }
    }
}

// ---------------------------------------------------------------------------
// kernel_launch
// inputs: 0:X int32[B,T]  1:W_xh f32[V,H]  2:W_hh f32[H,H]  3:b_h f32[H]
//         4:W_hq f32[H,V] 5:b_q f32[V]     out: f32[B,T,V]
// ---------------------------------------------------------------------------
extern "C" void kernel_launch(void* const* d_in, const int* in_sizes, int n_in,
                              void* d_out, int out_size)
{
    const int*   X   = (const int*)d_in[0];
    const float* Wxh = (const float*)d_in[1];
    const float* Whh = (const float*)d_in[2];
    const float* bh  = (const float*)d_in[3];
    const float* Whq = (const float*)d_in[4];
    const float* bq  = (const float*)d_in[5];
    float*       out = (float*)d_out;

    rnn_recurrence<<<BB / 8, 256>>>(X, Wxh, Whh, bh);
    rnn_logits<<<(TT * BB) / (NCHUNKS * CROWS), 256>>>(Whq, bq, out);
}

// round 9
// speedup vs baseline: 1.6520x; 1.2471x over previous
#include <cuda_runtime.h>
#include <cuda_bf16.h>

#define BB 1024
#define TT 256
#define VV 256
#define HH 32

// hs scratch, plain layout: g_hs[row][k], row = t*B + b  (33.5 MB, L2-resident)
__device__ float g_hs[TT * BB * HH];

__device__ __forceinline__ float htanh(float x) {
    float y;
    asm("tanh.approx.f32 %0, %1;" : "=f"(y) : "f"(x));
    return y;
}

// ---------------------------------------------------------------------------
// Kernel A: embedding gather + recurrence (unchanged, ~27us).
// ---------------------------------------------------------------------------
__global__ void __launch_bounds__(256)
rnn_recurrence(const int* __restrict__ X, const float* __restrict__ Wxh,
               const float* __restrict__ Whh, const float* __restrict__ bh)
{
    __shared__ float sWxh[VV * HH];       // 32 KB
    __shared__ int   sX[8][TT];           // 8 KB
    __shared__ float sH[2][8][HH];        // 2 KB double-buffered h vectors

    const int tid  = threadIdx.x;
    const int lane = tid & 31;
    const int warp = tid >> 5;
    const int b    = blockIdx.x * 8 + warp;

    {
        const float4* s = (const float4*)Wxh;
        float4*       d = (float4*)sWxh;
        #pragma unroll
        for (int i = tid; i < (VV * HH) / 4; i += 256) d[i] = s[i];
    }
    {
        const int4* s = (const int4*)(X + (long)blockIdx.x * 8 * TT);
        int4*       d = (int4*)&sX[0][0];
        #pragma unroll
        for (int i = tid; i < (8 * TT) / 4; i += 256) d[i] = s[i];
    }

    float w[HH];
    #pragma unroll
    for (int i = 0; i < HH; i++) w[i] = Whh[i * HH + lane];
    const float bhv = bh[lane];

    sH[0][warp][lane] = 0.f;
    __syncthreads();

    float* outp = g_hs + (long)b * HH + lane;

    int   tok = sX[warp][0];
    float xe  = sWxh[tok * HH + lane];

    #pragma unroll 2
    for (int t = 0; t < TT; t++) {
        const int tokn = sX[warp][(t + 1) & (TT - 1)];

        const float4* hr = (const float4*)&sH[t & 1][warp][0];
        float4 hv[8];
        #pragma unroll
        for (int k = 0; k < 8; k++) hv[k] = hr[k];

        float a[8];
        #pragma unroll
        for (int k = 0; k < 8; k++) a[k] = 0.f;
        #pragma unroll
        for (int k = 0; k < 8; k += 2) {
            a[k+0] = fmaf(hv[k+0].x, w[4*k + 0], a[k+0]);
            a[k+1] = fmaf(hv[k+0].y, w[4*k + 1], a[k+1]);
            a[k+0] = fmaf(hv[k+0].z, w[4*k + 2], a[k+0]);
            a[k+1] = fmaf(hv[k+0].w, w[4*k + 3], a[k+1]);
            a[k+0] = fmaf(hv[k+1].x, w[4*k + 4], a[k+0]);
            a[k+1] = fmaf(hv[k+1].y, w[4*k + 5], a[k+1]);
            a[k+0] = fmaf(hv[k+1].z, w[4*k + 6], a[k+0]);
            a[k+1] = fmaf(hv[k+1].w, w[4*k + 7], a[k+1]);
        }
        float s = (xe + bhv)
                + (((a[0] + a[1]) + (a[2] + a[3]))
                +  ((a[4] + a[5]) + (a[6] + a[7])));

        xe = sWxh[tokn * HH + lane];

        const float h = htanh(s);
        sH[(t + 1) & 1][warp][lane] = h;
        outp[(long)t * (BB * HH)] = h;
        __syncwarp();
    }
}

// ---------------------------------------------------------------------------
// bf16 helpers
// ---------------------------------------------------------------------------
__device__ __forceinline__ unsigned bf2_of(float lo, float hi) {
    // pack (lo, hi) floats -> bf16x2 (lo in low 16 bits)
    const __nv_bfloat162 v = __floats2bfloat162_rn(lo, hi);
    return *(const unsigned*)&v;
}
__device__ __forceinline__ float2 bf2_back(unsigned u) {
    const __nv_bfloat162 v = *(const __nv_bfloat162*)&u;
    return make_float2(__bfloat162float(v.x), __bfloat162float(v.y));
}

__device__ __forceinline__ void mma_bf16(
    float* c, const unsigned* a, unsigned b0, unsigned b1)
{
    asm("mma.sync.aligned.m16n8k16.row.col.f32.bf16.bf16.f32 "
        "{%0,%1,%2,%3}, {%4,%5,%6,%7}, {%8,%9}, {%0,%1,%2,%3};"
        : "+f"(c[0]), "+f"(c[1]), "+f"(c[2]), "+f"(c[3])
        : "r"(a[0]), "r"(a[1]), "r"(a[2]), "r"(a[3]), "r"(b0), "r"(b1));
}

// ---------------------------------------------------------------------------
// Kernel B: logits = hs[262144,32] @ W_hq[32,256] + bq via m16n8k16 bf16 mma,
// 3-pass hi/lo split (rel err ~1e-5):  a*w ~= ahi*whi + ahi*wlo + alo*whi.
// 512 blocks x 8 chunks x 64 rows. Warp (mstrip, nhalf): m16 x n128.
// W fragments precomputed per block into 32 KB SMEM as uint4
//   (whi_b0, whi_b1, wlo_b0, wlo_b1) per [ntile][kc][lane].
// ntiles in groups of 4 with independent accumulators (mma dep distance 4).
// 3 blocks/SM (smem 33 KB, regs <= 85).
// ---------------------------------------------------------------------------
#define NCHUNKS 8
#define CROWS   64

__global__ void __launch_bounds__(256, 3)
rnn_logits(const float* __restrict__ Whq, const float* __restrict__ bq,
           float* __restrict__ out)
{
    __shared__ uint4 sWfrag[32 * 2 * 32];   // 32 KB: [ntile][kc][lane]
    __shared__ float sbq[VV];               // 1 KB

    const int tid  = threadIdx.x;
    const int lane = tid & 31;
    const int warp = tid >> 5;
    const int gid  = lane >> 2;   // row-in-fragment
    const int tig  = lane & 3;    // col-in-fragment group

    // Build fragment-ordered, hi/lo-split bf16 W (once per block).
    // entry (nt, kc, lane): n = nt*8 + gid, k0 = kc*16 + 2*tig
    //   b0 holds W[k0][n], W[k0+1][n]; b1 holds W[k0+8][n], W[k0+9][n]
    for (int i = tid; i < 32 * 2 * 32; i += 256) {
        const int l_  = i & 31;
        const int kc_ = (i >> 5) & 1;
        const int nt_ = i >> 6;
        const int n   = nt_ * 8 + (l_ >> 2);
        const int k0  = kc_ * 16 + 2 * (l_ & 3);
        const float w00 = Whq[(k0 + 0) * VV + n];
        const float w01 = Whq[(k0 + 1) * VV + n];
        const float w10 = Whq[(k0 + 8) * VV + n];
        const float w11 = Whq[(k0 + 9) * VV + n];
        const unsigned hi0 = bf2_of(w00, w01);
        const unsigned hi1 = bf2_of(w10, w11);
        const float2 h0 = bf2_back(hi0);
        const float2 h1 = bf2_back(hi1);
        const unsigned lo0 = bf2_of(w00 - h0.x, w01 - h0.y);
        const unsigned lo1 = bf2_of(w10 - h1.x, w11 - h1.y);
        sWfrag[i] = make_uint4(hi0, hi1, lo0, lo1);
    }
    if (tid < VV / 4) ((float4*)sbq)[tid] = ((const float4*)bq)[tid];
    __syncthreads();

    const int mstrip = warp >> 1;     // 0..3
    const int nhalf  = warp & 1;      // 0..1

    for (int c = 0; c < NCHUNKS; c++) {
        const long rowbase = (long)blockIdx.x * (NCHUNKS * CROWS)
                           + c * CROWS + mstrip * 16;
        const long r0 = rowbase + gid;
        const long r1 = r0 + 8;

        // A fragments (hi/lo) for 2 k-chunks of 16
        unsigned ahi[2][4], alo[2][4];
        #pragma unroll
        for (int kc = 0; kc < 2; kc++) {
            const int cb = kc * 16 + 2 * tig;
            const float2 f0 = *(const float2*)&g_hs[r0 * HH + cb];
            const float2 f1 = *(const float2*)&g_hs[r1 * HH + cb];
            const float2 f2 = *(const float2*)&g_hs[r0 * HH + cb + 8];
            const float2 f3 = *(const float2*)&g_hs[r1 * HH + cb + 8];
            ahi[kc][0] = bf2_of(f0.x, f0.y);
            ahi[kc][1] = bf2_of(f1.x, f1.y);
            ahi[kc][2] = bf2_of(f2.x, f2.y);
            ahi[kc][3] = bf2_of(f3.x, f3.y);
            const float2 h0 = bf2_back(ahi[kc][0]);
            const float2 h1 = bf2_back(ahi[kc][1]);
            const float2 h2 = bf2_back(ahi[kc][2]);
            const float2 h3 = bf2_back(ahi[kc][3]);
            alo[kc][0] = bf2_of(f0.x - h0.x, f0.y - h0.y);
            alo[kc][1] = bf2_of(f1.x - h1.x, f1.y - h1.y);
            alo[kc][2] = bf2_of(f2.x - h2.x, f2.y - h2.y);
            alo[kc][3] = bf2_of(f3.x - h3.x, f3.y - h3.y);
        }

        const int t0 = (int)(r0 >> 10), b0i = (int)(r0 & 1023);
        const int t1 = (int)(r1 >> 10), b1i = (int)(r1 & 1023);
        float* o0 = out + ((long)b0i * TT + t0) * VV;
        float* o1 = out + ((long)b1i * TT + t1) * VV;

        // 4 groups of 4 ntiles; 4 independent accumulator sets per group
        #pragma unroll 1
        for (int g = 0; g < 4; g++) {
            float cc[4][4];
            #pragma unroll
            for (int q = 0; q < 4; q++) {
                const int n0 = nhalf * 128 + (g * 4 + q) * 8;
                const float2 bqp = *(const float2*)&sbq[n0 + 2 * tig];
                cc[q][0] = bqp.x; cc[q][1] = bqp.y;
                cc[q][2] = bqp.x; cc[q][3] = bqp.y;
            }

            #pragma unroll
            for (int kc = 0; kc < 2; kc++) {
                uint4 w[4];
                #pragma unroll
                for (int q = 0; q < 4; q++)
                    w[q] = sWfrag[((nhalf * 16 + g * 4 + q) * 2 + kc) * 32 + lane];

                #pragma unroll
                for (int q = 0; q < 4; q++)            // ahi * whi
                    mma_bf16(cc[q], ahi[kc], w[q].x, w[q].y);
                #pragma unroll
                for (int q = 0; q < 4; q++)            // ahi * wlo
                    mma_bf16(cc[q], ahi[kc], w[q].z, w[q].w);
                #pragma unroll
                for (int q = 0; q < 4; q++)            // alo * whi
                    mma_bf16(cc[q], alo[kc], w[q].x, w[q].y);
            }

            #pragma unroll
            for (int q = 0; q < 4; q++) {
                const int n0 = nhalf * 128 + (g * 4 + q) * 8;
                *(float2*)(o0 + n0 + 2 * tig) = make_float2(cc[q][0], cc[q][1]);
                *(float2*)(o1 + n0 + 2 * tig) = make_float2(cc[q][2], cc[q][3]);
            }
        }
    }
}

// ---------------------------------------------------------------------------
// kernel_launch
// inputs: 0:X int32[B,T]  1:W_xh f32[V,H]  2:W_hh f32[H,H]  3:b_h f32[H]
//         4:W_hq f32[H,V] 5:b_q f32[V]     out: f32[B,T,V]
// ---------------------------------------------------------------------------
extern "C" void kernel_launch(void* const* d_in, const int* in_sizes, int n_in,
                              void* d_out, int out_size)
{
    const int*   X   = (const int*)d_in[0];
    const float* Wxh = (const float*)d_in[1];
    const float* Whh = (const float*)d_in[2];
    const float* bh  = (const float*)d_in[3];
    const float* Whq = (const float*)d_in[4];
    const float* bq  = (const float*)d_in[5];
    float*       out = (float*)d_out;

    rnn_recurrence<<<BB / 8, 256>>>(X, Wxh, Whh, bh);
    rnn_logits<<<(TT * BB) / (NCHUNKS * CROWS), 256>>>(Whq, bq, out);
}

// round 10
// speedup vs baseline: 1.8315x; 1.1086x over previous
#include <cuda_runtime.h>
#include <cuda_bf16.h>

#define BB 1024
#define TT 256
#define VV 256
#define HH 32

// hs scratch, plain layout: g_hs[row][k], row = t*B + b  (33.5 MB, L2-resident)
__device__ float g_hs[TT * BB * HH];

__device__ __forceinline__ float htanh(float x) {
    float y;
    asm("tanh.approx.f32 %0, %1;" : "=f"(y) : "f"(x));
    return y;
}

// ---------------------------------------------------------------------------
// Kernel A: embedding gather + recurrence (unchanged, ~29us).
// ---------------------------------------------------------------------------
__global__ void __launch_bounds__(256)
rnn_recurrence(const int* __restrict__ X, const float* __restrict__ Wxh,
               const float* __restrict__ Whh, const float* __restrict__ bh)
{
    __shared__ float sWxh[VV * HH];       // 32 KB
    __shared__ int   sX[8][TT];           // 8 KB
    __shared__ float sH[2][8][HH];        // 2 KB double-buffered h vectors

    const int tid  = threadIdx.x;
    const int lane = tid & 31;
    const int warp = tid >> 5;
    const int b    = blockIdx.x * 8 + warp;

    {
        const float4* s = (const float4*)Wxh;
        float4*       d = (float4*)sWxh;
        #pragma unroll
        for (int i = tid; i < (VV * HH) / 4; i += 256) d[i] = s[i];
    }
    {
        const int4* s = (const int4*)(X + (long)blockIdx.x * 8 * TT);
        int4*       d = (int4*)&sX[0][0];
        #pragma unroll
        for (int i = tid; i < (8 * TT) / 4; i += 256) d[i] = s[i];
    }

    float w[HH];
    #pragma unroll
    for (int i = 0; i < HH; i++) w[i] = Whh[i * HH + lane];
    const float bhv = bh[lane];

    sH[0][warp][lane] = 0.f;
    __syncthreads();

    float* outp = g_hs + (long)b * HH + lane;

    int   tok = sX[warp][0];
    float xe  = sWxh[tok * HH + lane];

    #pragma unroll 2
    for (int t = 0; t < TT; t++) {
        const int tokn = sX[warp][(t + 1) & (TT - 1)];

        const float4* hr = (const float4*)&sH[t & 1][warp][0];
        float4 hv[8];
        #pragma unroll
        for (int k = 0; k < 8; k++) hv[k] = hr[k];

        float a[8];
        #pragma unroll
        for (int k = 0; k < 8; k++) a[k] = 0.f;
        #pragma unroll
        for (int k = 0; k < 8; k += 2) {
            a[k+0] = fmaf(hv[k+0].x, w[4*k + 0], a[k+0]);
            a[k+1] = fmaf(hv[k+0].y, w[4*k + 1], a[k+1]);
            a[k+0] = fmaf(hv[k+0].z, w[4*k + 2], a[k+0]);
            a[k+1] = fmaf(hv[k+0].w, w[4*k + 3], a[k+1]);
            a[k+0] = fmaf(hv[k+1].x, w[4*k + 4], a[k+0]);
            a[k+1] = fmaf(hv[k+1].y, w[4*k + 5], a[k+1]);
            a[k+0] = fmaf(hv[k+1].z, w[4*k + 6], a[k+0]);
            a[k+1] = fmaf(hv[k+1].w, w[4*k + 7], a[k+1]);
        }
        float s = (xe + bhv)
                + (((a[0] + a[1]) + (a[2] + a[3]))
                +  ((a[4] + a[5]) + (a[6] + a[7])));

        xe = sWxh[tokn * HH + lane];

        const float h = htanh(s);
        sH[(t + 1) & 1][warp][lane] = h;
        outp[(long)t * (BB * HH)] = h;
        __syncwarp();
    }
}

// ---------------------------------------------------------------------------
// bf16 helpers
// ---------------------------------------------------------------------------
__device__ __forceinline__ unsigned bf2_of(float lo, float hi) {
    const __nv_bfloat162 v = __floats2bfloat162_rn(lo, hi);
    return *(const unsigned*)&v;
}
__device__ __forceinline__ float2 bf2_back(unsigned u) {
    const __nv_bfloat162 v = *(const __nv_bfloat162*)&u;
    return make_float2(__bfloat162float(v.x), __bfloat162float(v.y));
}

__device__ __forceinline__ void mma_bf16(
    float* c, const unsigned* a, unsigned b0, unsigned b1)
{
    asm("mma.sync.aligned.m16n8k16.row.col.f32.bf16.bf16.f32 "
        "{%0,%1,%2,%3}, {%4,%5,%6,%7}, {%8,%9}, {%0,%1,%2,%3};"
        : "+f"(c[0]), "+f"(c[1]), "+f"(c[2]), "+f"(c[3])
        : "r"(a[0]), "r"(a[1]), "r"(a[2]), "r"(a[3]), "r"(b0), "r"(b1));
}

// ---------------------------------------------------------------------------
// Kernel B: logits = hs[262144,32] @ W_hq[32,256] + bq via m16n8k16 bf16 mma,
// 3-pass hi/lo split. PERSISTENT balanced grid: exactly 444 blocks
// (148 SM x 3 resident) grid-stride over 4096 chunks of 64 rows — one wave,
// no wave-quantization tail. Inner loop identical to round 9.
// ---------------------------------------------------------------------------
#define CROWS    64
#define NBLOCKS  444
#define NCHUNKT  ((TT * BB) / CROWS)   // 4096

__global__ void __launch_bounds__(256, 3)
rnn_logits(const float* __restrict__ Whq, const float* __restrict__ bq,
           float* __restrict__ out)
{
    __shared__ uint4 sWfrag[32 * 2 * 32];   // 32 KB: [ntile][kc][lane]
    __shared__ float sbq[VV];               // 1 KB

    const int tid  = threadIdx.x;
    const int lane = tid & 31;
    const int warp = tid >> 5;
    const int gid  = lane >> 2;   // row-in-fragment
    const int tig  = lane & 3;    // col-in-fragment group

    // Build fragment-ordered, hi/lo-split bf16 W (once per block).
    for (int i = tid; i < 32 * 2 * 32; i += 256) {
        const int l_  = i & 31;
        const int kc_ = (i >> 5) & 1;
        const int nt_ = i >> 6;
        const int n   = nt_ * 8 + (l_ >> 2);
        const int k0  = kc_ * 16 + 2 * (l_ & 3);
        const float w00 = Whq[(k0 + 0) * VV + n];
        const float w01 = Whq[(k0 + 1) * VV + n];
        const float w10 = Whq[(k0 + 8) * VV + n];
        const float w11 = Whq[(k0 + 9) * VV + n];
        const unsigned hi0 = bf2_of(w00, w01);
        const unsigned hi1 = bf2_of(w10, w11);
        const float2 h0 = bf2_back(hi0);
        const float2 h1 = bf2_back(hi1);
        const unsigned lo0 = bf2_of(w00 - h0.x, w01 - h0.y);
        const unsigned lo1 = bf2_of(w10 - h1.x, w11 - h1.y);
        sWfrag[i] = make_uint4(hi0, hi1, lo0, lo1);
    }
    if (tid < VV / 4) ((float4*)sbq)[tid] = ((const float4*)bq)[tid];
    __syncthreads();

    const int mstrip = warp >> 1;     // 0..3
    const int nhalf  = warp & 1;      // 0..1

    for (int ch = blockIdx.x; ch < NCHUNKT; ch += NBLOCKS) {
        const long rowbase = (long)ch * CROWS + mstrip * 16;
        const long r0 = rowbase + gid;
        const long r1 = r0 + 8;

        // A fragments (hi/lo) for 2 k-chunks of 16
        unsigned ahi[2][4], alo[2][4];
        #pragma unroll
        for (int kc = 0; kc < 2; kc++) {
            const int cb = kc * 16 + 2 * tig;
            const float2 f0 = *(const float2*)&g_hs[r0 * HH + cb];
            const float2 f1 = *(const float2*)&g_hs[r1 * HH + cb];
            const float2 f2 = *(const float2*)&g_hs[r0 * HH + cb + 8];
            const float2 f3 = *(const float2*)&g_hs[r1 * HH + cb + 8];
            ahi[kc][0] = bf2_of(f0.x, f0.y);
            ahi[kc][1] = bf2_of(f1.x, f1.y);
            ahi[kc][2] = bf2_of(f2.x, f2.y);
            ahi[kc][3] = bf2_of(f3.x, f3.y);
            const float2 h0 = bf2_back(ahi[kc][0]);
            const float2 h1 = bf2_back(ahi[kc][1]);
            const float2 h2 = bf2_back(ahi[kc][2]);
            const float2 h3 = bf2_back(ahi[kc][3]);
            alo[kc][0] = bf2_of(f0.x - h0.x, f0.y - h0.y);
            alo[kc][1] = bf2_of(f1.x - h1.x, f1.y - h1.y);
            alo[kc][2] = bf2_of(f2.x - h2.x, f2.y - h2.y);
            alo[kc][3] = bf2_of(f3.x - h3.x, f3.y - h3.y);
        }

        const int t0 = (int)(r0 >> 10), b0i = (int)(r0 & 1023);
        const int t1 = (int)(r1 >> 10), b1i = (int)(r1 & 1023);
        float* o0 = out + ((long)b0i * TT + t0) * VV;
        float* o1 = out + ((long)b1i * TT + t1) * VV;

        // 4 groups of 4 ntiles; 4 independent accumulator sets per group
        #pragma unroll 1
        for (int g = 0; g < 4; g++) {
            float cc[4][4];
            #pragma unroll
            for (int q = 0; q < 4; q++) {
                const int n0 = nhalf * 128 + (g * 4 + q) * 8;
                const float2 bqp = *(const float2*)&sbq[n0 + 2 * tig];
                cc[q][0] = bqp.x; cc[q][1] = bqp.y;
                cc[q][2] = bqp.x; cc[q][3] = bqp.y;
            }

            #pragma unroll
            for (int kc = 0; kc < 2; kc++) {
                uint4 w[4];
                #pragma unroll
                for (int q = 0; q < 4; q++)
                    w[q] = sWfrag[((nhalf * 16 + g * 4 + q) * 2 + kc) * 32 + lane];

                #pragma unroll
                for (int q = 0; q < 4; q++)            // ahi * whi
                    mma_bf16(cc[q], ahi[kc], w[q].x, w[q].y);
                #pragma unroll
                for (int q = 0; q < 4; q++)            // ahi * wlo
                    mma_bf16(cc[q], ahi[kc], w[q].z, w[q].w);
                #pragma unroll
                for (int q = 0; q < 4; q++)            // alo * whi
                    mma_bf16(cc[q], alo[kc], w[q].x, w[q].y);
            }

            #pragma unroll
            for (int q = 0; q < 4; q++) {
                const int n0 = nhalf * 128 + (g * 4 + q) * 8;
                *(float2*)(o0 + n0 + 2 * tig) = make_float2(cc[q][0], cc[q][1]);
                *(float2*)(o1 + n0 + 2 * tig) = make_float2(cc[q][2], cc[q][3]);
            }
        }
    }
}

// ---------------------------------------------------------------------------
// kernel_launch
// inputs: 0:X int32[B,T]  1:W_xh f32[V,H]  2:W_hh f32[H,H]  3:b_h f32[H]
//         4:W_hq f32[H,V] 5:b_q f32[V]     out: f32[B,T,V]
// ---------------------------------------------------------------------------
extern "C" void kernel_launch(void* const* d_in, const int* in_sizes, int n_in,
                              void* d_out, int out_size)
{
    const int*   X   = (const int*)d_in[0];
    const float* Wxh = (const float*)d_in[1];
    const float* Whh = (const float*)d_in[2];
    const float* bh  = (const float*)d_in[3];
    const float* Whq = (const float*)d_in[4];
    const float* bq  = (const float*)d_in[5];
    float*       out = (float*)d_out;

    rnn_recurrence<<<BB / 8, 256>>>(X, Wxh, Whh, bh);
    rnn_logits<<<NBLOCKS, 256>>>(Whq, bq, out);
}

// round 11
// speedup vs baseline: 1.9685x; 1.0748x over previous
#include <cuda_runtime.h>
#include <cuda_bf16.h>
#include <cuda_fp16.h>

#define BB 1024
#define TT 256
#define VV 256
#define HH 32

// hs scratch, plain layout: g_hs[row][k], row = t*B + b  (33.5 MB, L2-resident)
__device__ float g_hs[TT * BB * HH];

__device__ __forceinline__ float htanh(float x) {
    float y;
    asm("tanh.approx.f32 %0, %1;" : "=f"(y) : "f"(x));
    return y;
}

// ---------------------------------------------------------------------------
// Kernel A: embedding gather + recurrence (unchanged, ~28us).
// ---------------------------------------------------------------------------
__global__ void __launch_bounds__(256)
rnn_recurrence(const int* __restrict__ X, const float* __restrict__ Wxh,
               const float* __restrict__ Whh, const float* __restrict__ bh)
{
    __shared__ float sWxh[VV * HH];       // 32 KB
    __shared__ int   sX[8][TT];           // 8 KB
    __shared__ float sH[2][8][HH];        // 2 KB double-buffered h vectors

    const int tid  = threadIdx.x;
    const int lane = tid & 31;
    const int warp = tid >> 5;
    const int b    = blockIdx.x * 8 + warp;

    {
        const float4* s = (const float4*)Wxh;
        float4*       d = (float4*)sWxh;
        #pragma unroll
        for (int i = tid; i < (VV * HH) / 4; i += 256) d[i] = s[i];
    }
    {
        const int4* s = (const int4*)(X + (long)blockIdx.x * 8 * TT);
        int4*       d = (int4*)&sX[0][0];
        #pragma unroll
        for (int i = tid; i < (8 * TT) / 4; i += 256) d[i] = s[i];
    }

    float w[HH];
    #pragma unroll
    for (int i = 0; i < HH; i++) w[i] = Whh[i * HH + lane];
    const float bhv = bh[lane];

    sH[0][warp][lane] = 0.f;
    __syncthreads();

    float* outp = g_hs + (long)b * HH + lane;

    int   tok = sX[warp][0];
    float xe  = sWxh[tok * HH + lane];

    #pragma unroll 2
    for (int t = 0; t < TT; t++) {
        const int tokn = sX[warp][(t + 1) & (TT - 1)];

        const float4* hr = (const float4*)&sH[t & 1][warp][0];
        float4 hv[8];
        #pragma unroll
        for (int k = 0; k < 8; k++) hv[k] = hr[k];

        float a[8];
        #pragma unroll
        for (int k = 0; k < 8; k++) a[k] = 0.f;
        #pragma unroll
        for (int k = 0; k < 8; k += 2) {
            a[k+0] = fmaf(hv[k+0].x, w[4*k + 0], a[k+0]);
            a[k+1] = fmaf(hv[k+0].y, w[4*k + 1], a[k+1]);
            a[k+0] = fmaf(hv[k+0].z, w[4*k + 2], a[k+0]);
            a[k+1] = fmaf(hv[k+0].w, w[4*k + 3], a[k+1]);
            a[k+0] = fmaf(hv[k+1].x, w[4*k + 4], a[k+0]);
            a[k+1] = fmaf(hv[k+1].y, w[4*k + 5], a[k+1]);
            a[k+0] = fmaf(hv[k+1].z, w[4*k + 6], a[k+0]);
            a[k+1] = fmaf(hv[k+1].w, w[4*k + 7], a[k+1]);
        }
        float s = (xe + bhv)
                + (((a[0] + a[1]) + (a[2] + a[3]))
                +  ((a[4] + a[5]) + (a[6] + a[7])));

        xe = sWxh[tokn * HH + lane];

        const float h = htanh(s);
        sH[(t + 1) & 1][warp][lane] = h;
        outp[(long)t * (BB * HH)] = h;
        __syncwarp();
    }
}

// ---------------------------------------------------------------------------
// fp16 helpers
// ---------------------------------------------------------------------------
__device__ __forceinline__ unsigned h2_of(float lo, float hi) {
    const __half2 v = __floats2half2_rn(lo, hi);
    return *(const unsigned*)&v;
}
__device__ __forceinline__ float2 h2_back(unsigned u) {
    const __half2 v = *(const __half2*)&u;
    return make_float2(__half2float(v.x), __half2float(v.y));
}

__device__ __forceinline__ void mma_f16(
    float* c, const unsigned* a, unsigned b0, unsigned b1)
{
    asm("mma.sync.aligned.m16n8k16.row.col.f32.f16.f16.f32 "
        "{%0,%1,%2,%3}, {%4,%5,%6,%7}, {%8,%9}, {%0,%1,%2,%3};"
        : "+f"(c[0]), "+f"(c[1]), "+f"(c[2]), "+f"(c[3])
        : "r"(a[0]), "r"(a[1]), "r"(a[2]), "r"(a[3]), "r"(b0), "r"(b1));
}

// ---------------------------------------------------------------------------
// Kernel B: logits = hs[262144,32] @ W_hq[32,256] + bq via m16n8k16 fp16 mma,
// 2-pass exact-A split:  a = ahi + alo (exact in fp16 pair),
//   a*w16 = ahi*w16 + alo*w16  (only W->fp16 rounding remains, ~2.8e-4 rel).
// Persistent 444-block grid (148 SM x 3), grid-stride over 4096 chunks of 64
// rows. W fragments (fp16) precomputed per block into 16 KB SMEM as uint2.
// ntiles in groups of 4 with independent accumulators.
// ---------------------------------------------------------------------------
#define CROWS    64
#define NBLOCKS  444
#define NCHUNKT  ((TT * BB) / CROWS)   // 4096

__global__ void __launch_bounds__(256, 3)
rnn_logits(const float* __restrict__ Whq, const float* __restrict__ bq,
           float* __restrict__ out)
{
    __shared__ uint2 sWfrag[32 * 2 * 32];   // 16 KB: [ntile][kc][lane]
    __shared__ float sbq[VV];               // 1 KB

    const int tid  = threadIdx.x;
    const int lane = tid & 31;
    const int warp = tid >> 5;
    const int gid  = lane >> 2;   // row-in-fragment
    const int tig  = lane & 3;    // col-in-fragment group

    // Build fragment-ordered fp16 W (once per block).
    // entry (nt, kc, lane): n = nt*8 + gid, k0 = kc*16 + 2*tig
    //   x holds W[k0][n], W[k0+1][n];  y holds W[k0+8][n], W[k0+9][n]
    for (int i = tid; i < 32 * 2 * 32; i += 256) {
        const int l_  = i & 31;
        const int kc_ = (i >> 5) & 1;
        const int nt_ = i >> 6;
        const int n   = nt_ * 8 + (l_ >> 2);
        const int k0  = kc_ * 16 + 2 * (l_ & 3);
        const float w00 = Whq[(k0 + 0) * VV + n];
        const float w01 = Whq[(k0 + 1) * VV + n];
        const float w10 = Whq[(k0 + 8) * VV + n];
        const float w11 = Whq[(k0 + 9) * VV + n];
        sWfrag[i] = make_uint2(h2_of(w00, w01), h2_of(w10, w11));
    }
    if (tid < VV / 4) ((float4*)sbq)[tid] = ((const float4*)bq)[tid];
    __syncthreads();

    const int mstrip = warp >> 1;     // 0..3
    const int nhalf  = warp & 1;      // 0..1

    for (int ch = blockIdx.x; ch < NCHUNKT; ch += NBLOCKS) {
        const long rowbase = (long)ch * CROWS + mstrip * 16;
        const long r0 = rowbase + gid;
        const long r1 = r0 + 8;

        // A fragments: exact hi/lo fp16 split, 2 k-chunks of 16
        unsigned ahi[2][4], alo[2][4];
        #pragma unroll
        for (int kc = 0; kc < 2; kc++) {
            const int cb = kc * 16 + 2 * tig;
            const float2 f0 = *(const float2*)&g_hs[r0 * HH + cb];
            const float2 f1 = *(const float2*)&g_hs[r1 * HH + cb];
            const float2 f2 = *(const float2*)&g_hs[r0 * HH + cb + 8];
            const float2 f3 = *(const float2*)&g_hs[r1 * HH + cb + 8];
            ahi[kc][0] = h2_of(f0.x, f0.y);
            ahi[kc][1] = h2_of(f1.x, f1.y);
            ahi[kc][2] = h2_of(f2.x, f2.y);
            ahi[kc][3] = h2_of(f3.x, f3.y);
            const float2 h0 = h2_back(ahi[kc][0]);
            const float2 h1 = h2_back(ahi[kc][1]);
            const float2 h2 = h2_back(ahi[kc][2]);
            const float2 h3 = h2_back(ahi[kc][3]);
            alo[kc][0] = h2_of(f0.x - h0.x, f0.y - h0.y);
            alo[kc][1] = h2_of(f1.x - h1.x, f1.y - h1.y);
            alo[kc][2] = h2_of(f2.x - h2.x, f2.y - h2.y);
            alo[kc][3] = h2_of(f3.x - h3.x, f3.y - h3.y);
        }

        const int t0 = (int)(r0 >> 10), b0i = (int)(r0 & 1023);
        const int t1 = (int)(r1 >> 10), b1i = (int)(r1 & 1023);
        float* o0 = out + ((long)b0i * TT + t0) * VV;
        float* o1 = out + ((long)b1i * TT + t1) * VV;

        // 4 groups of 4 ntiles; independent accumulator sets per group
        #pragma unroll 1
        for (int g = 0; g < 4; g++) {
            float cc[4][4];
            #pragma unroll
            for (int q = 0; q < 4; q++) {
                const int n0 = nhalf * 128 + (g * 4 + q) * 8;
                const float2 bqp = *(const float2*)&sbq[n0 + 2 * tig];
                cc[q][0] = bqp.x; cc[q][1] = bqp.y;
                cc[q][2] = bqp.x; cc[q][3] = bqp.y;
            }

            #pragma unroll
            for (int kc = 0; kc < 2; kc++) {
                uint2 w[4];
                #pragma unroll
                for (int q = 0; q < 4; q++)
                    w[q] = sWfrag[((nhalf * 16 + g * 4 + q) * 2 + kc) * 32 + lane];

                #pragma unroll
                for (int q = 0; q < 4; q++)            // ahi * w
                    mma_f16(cc[q], ahi[kc], w[q].x, w[q].y);
                #pragma unroll
                for (int q = 0; q < 4; q++)            // alo * w
                    mma_f16(cc[q], alo[kc], w[q].x, w[q].y);
            }

            #pragma unroll
            for (int q = 0; q < 4; q++) {
                const int n0 = nhalf * 128 + (g * 4 + q) * 8;
                *(float2*)(o0 + n0 + 2 * tig) = make_float2(cc[q][0], cc[q][1]);
                *(float2*)(o1 + n0 + 2 * tig) = make_float2(cc[q][2], cc[q][3]);
            }
        }
    }
}

// ---------------------------------------------------------------------------
// kernel_launch
// inputs: 0:X int32[B,T]  1:W_xh f32[V,H]  2:W_hh f32[H,H]  3:b_h f32[H]
//         4:W_hq f32[H,V] 5:b_q f32[V]     out: f32[B,T,V]
// ---------------------------------------------------------------------------
extern "C" void kernel_launch(void* const* d_in, const int* in_sizes, int n_in,
                              void* d_out, int out_size)
{
    const int*   X   = (const int*)d_in[0];
    const float* Wxh = (const float*)d_in[1];
    const float* Whh = (const float*)d_in[2];
    const float* bh  = (const float*)d_in[3];
    const float* Whq = (const float*)d_in[4];
    const float* bq  = (const float*)d_in[5];
    float*       out = (float*)d_out;

    rnn_recurrence<<<BB / 8, 256>>>(X, Wxh, Whh, bh);
    rnn_logits<<<NBLOCKS, 256>>>(Whq, bq, out);
}